// round 1
// baseline (speedup 1.0000x reference)
#include <cuda_runtime.h>
#include <cstdint>

#define N_NODES 16384
#define HDIM    64
#define MAXN    160          // max nnz/row: Binomial(16384,0.004)+1, mean 66, 160 is ~11 sigma
#define NBLK    1024         // gemm blocks (16 rows each)
#define BN_EPS  1e-5f

// ---------------- device scratch (no allocations allowed) ----------------
__device__ int   g_idx[N_NODES * MAXN];     // CSR-ish column indices per row
__device__ int   g_nnz[N_NODES];            // row degree (= row sum of adj)
__device__ float g_pooled[N_NODES * HDIM];
__device__ float g_t[N_NODES * HDIM];
__device__ float g_t2[N_NODES * HDIM];
__device__ float g_h[N_NODES * HDIM];
__device__ float g_part[NBLK * 128];        // per-block [sum(64) | sumsq(64)]
__device__ float g_ab[128];                 // BN affine: a[64], b[64]

// ---------------- K1: stream adj once, build index lists + degrees ----------------
// One warp per row. Fast path: 8-word OR test per thread (32B), rare slow path
// compacts nonzero columns via per-warp shared counter. Order of indices is
// irrelevant (commutative fp32 sums, within tolerance).
__global__ __launch_bounds__(256) void scan_adj(const float* __restrict__ adj) {
    int lane   = threadIdx.x & 31;
    int wlocal = threadIdx.x >> 5;
    int row    = (blockIdx.x << 3) + wlocal;        // 2048 blocks * 8 warps

    __shared__ int snnz[8];
    if (lane == 0) snnz[wlocal] = 0;
    __syncwarp();

    const uint4* base = reinterpret_cast<const uint4*>(adj + (size_t)row * N_NODES);
    int* rowidx = g_idx + (size_t)row * MAXN;

    #pragma unroll 4
    for (int t = 0; t < 64; t++) {
        int f4 = t * 64 + lane * 2;                 // warp covers 1KB contiguous
        uint4 a = base[f4];
        uint4 b = base[f4 + 1];
        unsigned m = (a.x | a.y | a.z | a.w) | (b.x | b.y | b.z | b.w);
        if (m) {
            unsigned w[8] = {a.x, a.y, a.z, a.w, b.x, b.y, b.z, b.w};
            int col0 = f4 * 4;
            int loc[8];
            int cnt = 0;
            #pragma unroll
            for (int k = 0; k < 8; k++)
                if (w[k]) loc[cnt++] = col0 + k;
            int pos = atomicAdd(&snnz[wlocal], cnt);
            if (pos + cnt <= MAXN) {
                for (int i = 0; i < cnt; i++) rowidx[pos + i] = loc[i];
            }
        }
    }
    __syncwarp();
    if (lane == 0) g_nnz[row] = snnz[wlocal];
}

// ---------------- K2: sparse mean aggregation: out[r,:] = mean_{j in nbr(r)} src[j,:] ----------------
__global__ __launch_bounds__(64) void agg(const float* __restrict__ src,
                                          float* __restrict__ out) {
    int r = blockIdx.x;
    int c = threadIdx.x;                    // 64 threads = one per column
    __shared__ int ids[MAXN];
    int nnz = g_nnz[r];
    for (int i = c; i < nnz; i += 64) ids[i] = g_idx[(size_t)r * MAXN + i];
    __syncthreads();

    float a0 = 0.f, a1 = 0.f, a2 = 0.f, a3 = 0.f;
    int k = 0;
    for (; k + 4 <= nnz; k += 4) {
        a0 += src[(size_t)ids[k]     * HDIM + c];
        a1 += src[(size_t)ids[k + 1] * HDIM + c];
        a2 += src[(size_t)ids[k + 2] * HDIM + c];
        a3 += src[(size_t)ids[k + 3] * HDIM + c];
    }
    for (; k < nnz; k++) a0 += src[(size_t)ids[k] * HDIM + c];
    out[(size_t)r * HDIM + c] = ((a0 + a1) + (a2 + a3)) / (float)nnz;
}

// ---------------- K3: fused GEMM [16384,64]@[64,64] + bias, with per-column
// sum/sumsq partials for BN. MODE==1 applies relu(a*x+b) (previous BN) to input.
template <int MODE>
__global__ __launch_bounds__(256) void gemm64(const float* __restrict__ in,
                                              const float* __restrict__ W,
                                              const float* __restrict__ bias,
                                              float* __restrict__ out,
                                              float* __restrict__ part) {
    __shared__ float Ws[64 * 64];
    __shared__ float Is[16][68];            // padded vs bank conflicts

    int tid = threadIdx.x;
    for (int i = tid; i < 4096; i += 256) Ws[i] = W[i];

    int row0 = blockIdx.x * 16;
    for (int i = tid; i < 1024; i += 256) {
        int rr = i >> 6, cc = i & 63;
        float v = in[(size_t)(row0 + rr) * HDIM + cc];
        if (MODE == 1)
            v = fmaxf(fmaf(g_ab[cc], v, g_ab[64 + cc]), 0.f);
        Is[rr][cc] = v;
    }
    __syncthreads();

    int ty = tid >> 4;          // output row within tile
    int tx = tid & 15;          // 4-col group
    float acc[4];
    #pragma unroll
    for (int j = 0; j < 4; j++) acc[j] = bias[tx * 4 + j];

    #pragma unroll
    for (int k = 0; k < 64; k++) {
        float iv = Is[ty][k];
        #pragma unroll
        for (int j = 0; j < 4; j++)
            acc[j] = fmaf(iv, Ws[k * 64 + tx * 4 + j], acc[j]);
    }

    size_t obase = (size_t)(row0 + ty) * HDIM + tx * 4;
    #pragma unroll
    for (int j = 0; j < 4; j++) out[obase + j] = acc[j];

    // per-block column stats (sum, sumsq) -> g_part (no atomics, deterministic)
    __syncthreads();
    #pragma unroll
    for (int j = 0; j < 4; j++) Is[ty][tx * 4 + j] = acc[j];
    __syncthreads();
    if (tid < 64) {
        float s = 0.f;
        #pragma unroll
        for (int r = 0; r < 16; r++) s += Is[r][tid];
        part[(size_t)blockIdx.x * 128 + tid] = s;
    }
    __syncthreads();
    #pragma unroll
    for (int j = 0; j < 4; j++) Is[ty][tx * 4 + j] = acc[j] * acc[j];
    __syncthreads();
    if (tid < 64) {
        float s = 0.f;
        #pragma unroll
        for (int r = 0; r < 16; r++) s += Is[r][tid];
        part[(size_t)blockIdx.x * 128 + 64 + tid] = s;
    }
}

// ---------------- K4: reduce partials -> BN affine coefficients ----------------
__global__ __launch_bounds__(64) void bn_finalize(const float* __restrict__ g,
                                                  const float* __restrict__ be) {
    int c = threadIdx.x;
    float s = 0.f, q = 0.f;
    for (int b = 0; b < NBLK; b++) {
        s += g_part[(size_t)b * 128 + c];
        q += g_part[(size_t)b * 128 + 64 + c];
    }
    const float invn = 1.0f / (float)N_NODES;
    float mean = s * invn;
    float var  = q * invn - mean * mean;
    float a = g[c] * rsqrtf(var + BN_EPS);
    g_ab[c]      = a;
    g_ab[64 + c] = be[c] - mean * a;
}

// ---------------- K5: elementwise h = relu(a*t2 + b) ----------------
__global__ __launch_bounds__(256) void apply_bn_relu(const float* __restrict__ t2,
                                                     float* __restrict__ h) {
    int i = blockIdx.x * 256 + threadIdx.x;
    int c = i & 63;
    h[i] = fmaxf(fmaf(g_ab[c], t2[i], g_ab[64 + c]), 0.f);
}

// ---------------- K6: pooled_h = graph_pool @ h  (general dense, zero-skip) ----------------
__global__ __launch_bounds__(256) void pool(const float* __restrict__ gp,
                                            const float* __restrict__ h,
                                            float* __restrict__ out) {
    int g = blockIdx.x;                 // 128 graphs
    int c    = threadIdx.x & 63;
    int lane = threadIdx.x >> 6;        // 4 node-lanes (warp-uniform)
    const float* gprow = gp + (size_t)g * N_NODES;

    float acc = 0.f;
    for (int n0 = lane; n0 < N_NODES; n0 += 32) {
        #pragma unroll
        for (int u = 0; u < 8; u++) {
            int n = n0 + u * 4;
            float w = gprow[n];
            if (w != 0.f) acc = fmaf(w, h[(size_t)n * HDIM + c], acc);
        }
    }
    __shared__ float red[4][64];
    red[lane][c] = acc;
    __syncthreads();
    if (threadIdx.x < 64)
        out[(size_t)g * HDIM + threadIdx.x] =
            (red[0][threadIdx.x] + red[1][threadIdx.x]) +
            (red[2][threadIdx.x] + red[3][threadIdx.x]);
}

// ---------------- launch ----------------
extern "C" void kernel_launch(void* const* d_in, const int* in_sizes, int n_in,
                              void* d_out, int out_size) {
    const float* x   = (const float*)d_in[0];
    const float* adj = (const float*)d_in[1];
    const float* gp  = (const float*)d_in[2];

    // layer params: [W1, b1, g1, be1, W2, b2, g, be] x 2 starting at d_in[3]
    const float* P[16];
    for (int i = 0; i < 16; i++) P[i] = (const float*)d_in[3 + i];

    float* out      = (float*)d_out;
    float* h_nodes  = out + 128 * HDIM;   // [16384,64] after the [128,64] readout

    float *pooled, *t, *t2, *h0, *part;
    cudaGetSymbolAddress((void**)&pooled, g_pooled);
    cudaGetSymbolAddress((void**)&t,      g_t);
    cudaGetSymbolAddress((void**)&t2,     g_t2);
    cudaGetSymbolAddress((void**)&h0,     g_h);
    cudaGetSymbolAddress((void**)&part,   g_part);

    // 1) one pass over adj -> CSR indices + degrees
    scan_adj<<<2048, 256>>>(adj);

    // ---- layer 0 ----
    agg<<<N_NODES, 64>>>(x, pooled);
    gemm64<0><<<NBLK, 256>>>(pooled, P[0], P[1], t, part);
    bn_finalize<<<1, 64>>>(P[2], P[3]);                 // g1_0, be1_0
    gemm64<1><<<NBLK, 256>>>(t, P[4], P[5], t2, part);
    bn_finalize<<<1, 64>>>(P[6], P[7]);                 // g_0, be_0
    apply_bn_relu<<<(N_NODES * HDIM) / 256, 256>>>(t2, h0);

    // ---- layer 1 ----
    agg<<<N_NODES, 64>>>(h0, pooled);
    gemm64<0><<<NBLK, 256>>>(pooled, P[8], P[9], t, part);
    bn_finalize<<<1, 64>>>(P[10], P[11]);               // g1_1, be1_1
    gemm64<1><<<NBLK, 256>>>(t, P[12], P[13], t2, part);
    bn_finalize<<<1, 64>>>(P[14], P[15]);               // g_1, be_1
    apply_bn_relu<<<(N_NODES * HDIM) / 256, 256>>>(t2, h_nodes);

    // ---- graph readout ----
    pool<<<128, 256>>>(gp, h_nodes, out);

    (void)in_sizes; (void)n_in; (void)out_size;
}

// round 2
// speedup vs baseline: 1.1934x; 1.1934x over previous
#include <cuda_runtime.h>
#include <cstdint>

#define N_NODES 16384
#define HDIM    64
#define MAXN    160          // max nnz/row: Binomial(16384,0.004)+1, mean 66, ~11 sigma headroom
#define NBLK    1024         // gemm blocks (16 rows each)
#define BN_EPS  1e-5f

// ---------------- device scratch (no allocations allowed) ----------------
__device__ int   g_idx[N_NODES * MAXN];     // CSR-ish column indices per row
__device__ int   g_nnz[N_NODES];            // row degree (= row sum of adj)
__device__ float g_pooled[N_NODES * HDIM];
__device__ float g_t[N_NODES * HDIM];
__device__ float g_t2[N_NODES * HDIM];
__device__ float g_part[NBLK * 128];        // per-block [sum(64) | sumsq(64)]
__device__ float g_ab[128];                 // BN affine: a[64], b[64]

// ---------------- K1: stream adj once, build index lists + degrees ----------------
__global__ __launch_bounds__(256) void scan_adj(const float* __restrict__ adj) {
    int lane   = threadIdx.x & 31;
    int wlocal = threadIdx.x >> 5;
    int row    = (blockIdx.x << 3) + wlocal;        // 2048 blocks * 8 warps

    __shared__ int snnz[8];
    if (lane == 0) snnz[wlocal] = 0;
    __syncwarp();

    const uint4* base = reinterpret_cast<const uint4*>(adj + (size_t)row * N_NODES);
    int* rowidx = g_idx + (size_t)row * MAXN;

    #pragma unroll 4
    for (int t = 0; t < 64; t++) {
        int f4 = t * 64 + lane * 2;                 // warp covers 1KB contiguous
        uint4 a = base[f4];
        uint4 b = base[f4 + 1];
        unsigned m = (a.x | a.y | a.z | a.w) | (b.x | b.y | b.z | b.w);
        if (m) {
            unsigned w[8] = {a.x, a.y, a.z, a.w, b.x, b.y, b.z, b.w};
            int col0 = f4 * 4;
            int loc[8];
            int cnt = 0;
            #pragma unroll
            for (int k = 0; k < 8; k++)
                if (w[k]) loc[cnt++] = col0 + k;
            int pos = atomicAdd(&snnz[wlocal], cnt);
            if (pos + cnt <= MAXN) {
                for (int i = 0; i < cnt; i++) rowidx[pos + i] = loc[i];
            }
        }
    }
    __syncwarp();
    if (lane == 0) g_nnz[row] = snnz[wlocal];
}

// ---------------- K2: sparse mean aggregation ----------------
// out[r,:] = mean_{j in nbr(r)} f(src[j,:]);  f = identity (APPLY=0) or
// relu(a*x+b) using g_ab (APPLY=1, fuses previous layer's outer BN+ReLU).
template <int APPLY>
__global__ __launch_bounds__(64) void agg(const float* __restrict__ src,
                                          float* __restrict__ out) {
    int r = blockIdx.x;
    int c = threadIdx.x;                    // 64 threads = one per column
    __shared__ int ids[MAXN];
    int nnz = g_nnz[r];
    for (int i = c; i < nnz; i += 64) ids[i] = g_idx[(size_t)r * MAXN + i];
    __syncthreads();

    float bn_a = 0.f, bn_b = 0.f;
    if (APPLY) { bn_a = g_ab[c]; bn_b = g_ab[64 + c]; }

    float a0 = 0.f, a1 = 0.f, a2 = 0.f, a3 = 0.f;
    int k = 0;
    for (; k + 4 <= nnz; k += 4) {
        float v0 = src[(size_t)ids[k]     * HDIM + c];
        float v1 = src[(size_t)ids[k + 1] * HDIM + c];
        float v2 = src[(size_t)ids[k + 2] * HDIM + c];
        float v3 = src[(size_t)ids[k + 3] * HDIM + c];
        if (APPLY) {
            v0 = fmaxf(fmaf(bn_a, v0, bn_b), 0.f);
            v1 = fmaxf(fmaf(bn_a, v1, bn_b), 0.f);
            v2 = fmaxf(fmaf(bn_a, v2, bn_b), 0.f);
            v3 = fmaxf(fmaf(bn_a, v3, bn_b), 0.f);
        }
        a0 += v0; a1 += v1; a2 += v2; a3 += v3;
    }
    for (; k < nnz; k++) {
        float v = src[(size_t)ids[k] * HDIM + c];
        if (APPLY) v = fmaxf(fmaf(bn_a, v, bn_b), 0.f);
        a0 += v;
    }
    out[(size_t)r * HDIM + c] = ((a0 + a1) + (a2 + a3)) / (float)nnz;
}

// ---------------- K3: fused GEMM [16384,64]@[64,64] + bias + BN-stat partials
// MODE==1 applies relu(a*x+b) (previous inner BN) to the input tile.
template <int MODE>
__global__ __launch_bounds__(256) void gemm64(const float* __restrict__ in,
                                              const float* __restrict__ W,
                                              const float* __restrict__ bias,
                                              float* __restrict__ out,
                                              float* __restrict__ part) {
    __shared__ float Ws[64 * 64];
    __shared__ float Is[16][68];            // padded vs bank conflicts

    int tid = threadIdx.x;
    for (int i = tid; i < 4096; i += 256) Ws[i] = W[i];

    int row0 = blockIdx.x * 16;
    for (int i = tid; i < 1024; i += 256) {
        int rr = i >> 6, cc = i & 63;
        float v = in[(size_t)(row0 + rr) * HDIM + cc];
        if (MODE == 1)
            v = fmaxf(fmaf(g_ab[cc], v, g_ab[64 + cc]), 0.f);
        Is[rr][cc] = v;
    }
    __syncthreads();

    int ty = tid >> 4;          // output row within tile
    int tx = tid & 15;          // 4-col group
    float acc[4];
    #pragma unroll
    for (int j = 0; j < 4; j++) acc[j] = bias[tx * 4 + j];

    #pragma unroll
    for (int k = 0; k < 64; k++) {
        float iv = Is[ty][k];
        #pragma unroll
        for (int j = 0; j < 4; j++)
            acc[j] = fmaf(iv, Ws[k * 64 + tx * 4 + j], acc[j]);
    }

    size_t obase = (size_t)(row0 + ty) * HDIM + tx * 4;
    #pragma unroll
    for (int j = 0; j < 4; j++) out[obase + j] = acc[j];

    // per-block column stats (sum, sumsq) -> g_part (deterministic, no atomics)
    __syncthreads();
    #pragma unroll
    for (int j = 0; j < 4; j++) Is[ty][tx * 4 + j] = acc[j];
    __syncthreads();
    if (tid < 64) {
        float s = 0.f;
        #pragma unroll
        for (int r = 0; r < 16; r++) s += Is[r][tid];
        part[(size_t)blockIdx.x * 128 + tid] = s;
    }
    __syncthreads();
    #pragma unroll
    for (int j = 0; j < 4; j++) Is[ty][tx * 4 + j] = acc[j] * acc[j];
    __syncthreads();
    if (tid < 64) {
        float s = 0.f;
        #pragma unroll
        for (int r = 0; r < 16; r++) s += Is[r][tid];
        part[(size_t)blockIdx.x * 128 + 64 + tid] = s;
    }
}

// ---------------- K4: reduce partials -> BN affine coefficients ----------------
// 1024 threads: 16 segments x 64 columns, then shared tree reduce.
__global__ __launch_bounds__(1024) void bn_finalize(const float* __restrict__ g,
                                                    const float* __restrict__ be) {
    int tid = threadIdx.x;
    int c   = tid & 63;
    int seg = tid >> 6;                      // 0..15, 64 blocks each
    const float* p = g_part + (size_t)seg * 64 * 128;

    float s = 0.f, q = 0.f;
    #pragma unroll 8
    for (int b = 0; b < 64; b++) {
        s += p[(size_t)b * 128 + c];
        q += p[(size_t)b * 128 + 64 + c];
    }
    __shared__ float ss[16][64];
    __shared__ float qq[16][64];
    ss[seg][c] = s;
    qq[seg][c] = q;
    __syncthreads();

    if (tid < 64) {
        float S = 0.f, Q = 0.f;
        #pragma unroll
        for (int i = 0; i < 16; i++) { S += ss[i][tid]; Q += qq[i][tid]; }
        const float invn = 1.0f / (float)N_NODES;
        float mean = S * invn;
        float var  = Q * invn - mean * mean;
        float a = g[tid] * rsqrtf(var + BN_EPS);
        g_ab[tid]      = a;
        g_ab[64 + tid] = be[tid] - mean * a;
    }
}

// ---------------- K5: elementwise h = relu(a*t2 + b) (final layer only) ----------------
__global__ __launch_bounds__(256) void apply_bn_relu(const float* __restrict__ t2,
                                                     float* __restrict__ h) {
    int i = blockIdx.x * 256 + threadIdx.x;
    int c = i & 63;
    h[i] = fmaxf(fmaf(g_ab[c], t2[i], g_ab[64 + c]), 0.f);
}

// ---------------- K6: pooled_h = graph_pool @ h  (general dense, zero-skip) ----------------
__global__ __launch_bounds__(256) void pool(const float* __restrict__ gp,
                                            const float* __restrict__ h,
                                            float* __restrict__ out) {
    int g = blockIdx.x;                 // 128 graphs
    int c    = threadIdx.x & 63;
    int lane = threadIdx.x >> 6;        // 4 node-lanes (warp-uniform)
    const float* gprow = gp + (size_t)g * N_NODES;

    float acc = 0.f;
    for (int n0 = lane; n0 < N_NODES; n0 += 32) {
        #pragma unroll
        for (int u = 0; u < 8; u++) {
            int n = n0 + u * 4;
            float w = gprow[n];
            if (w != 0.f) acc = fmaf(w, h[(size_t)n * HDIM + c], acc);
        }
    }
    __shared__ float red[4][64];
    red[lane][c] = acc;
    __syncthreads();
    if (threadIdx.x < 64)
        out[(size_t)g * HDIM + threadIdx.x] =
            (red[0][threadIdx.x] + red[1][threadIdx.x]) +
            (red[2][threadIdx.x] + red[3][threadIdx.x]);
}

// ---------------- launch ----------------
extern "C" void kernel_launch(void* const* d_in, const int* in_sizes, int n_in,
                              void* d_out, int out_size) {
    const float* x   = (const float*)d_in[0];
    const float* adj = (const float*)d_in[1];
    const float* gp  = (const float*)d_in[2];

    const float* P[16];
    for (int i = 0; i < 16; i++) P[i] = (const float*)d_in[3 + i];

    float* out      = (float*)d_out;
    float* h_nodes  = out + 128 * HDIM;   // [16384,64] after the [128,64] readout

    float *pooled, *t, *t2, *part;
    cudaGetSymbolAddress((void**)&pooled, g_pooled);
    cudaGetSymbolAddress((void**)&t,      g_t);
    cudaGetSymbolAddress((void**)&t2,     g_t2);
    cudaGetSymbolAddress((void**)&part,   g_part);

    // 1) one pass over adj -> CSR indices + degrees
    scan_adj<<<2048, 256>>>(adj);

    // ---- layer 0 ----
    agg<0><<<N_NODES, 64>>>(x, pooled);
    gemm64<0><<<NBLK, 256>>>(pooled, P[0], P[1], t, part);
    bn_finalize<<<1, 1024>>>(P[2], P[3]);               // g1_0, be1_0
    gemm64<1><<<NBLK, 256>>>(t, P[4], P[5], t2, part);
    bn_finalize<<<1, 1024>>>(P[6], P[7]);               // g_0, be_0

    // ---- layer 1 (outer BN+ReLU of layer 0 fused into the gather) ----
    agg<1><<<N_NODES, 64>>>(t2, pooled);
    gemm64<0><<<NBLK, 256>>>(pooled, P[8], P[9], t, part);
    bn_finalize<<<1, 1024>>>(P[10], P[11]);             // g1_1, be1_1
    gemm64<1><<<NBLK, 256>>>(t, P[12], P[13], t2, part);
    bn_finalize<<<1, 1024>>>(P[14], P[15]);             // g_1, be_1
    apply_bn_relu<<<(N_NODES * HDIM) / 256, 256>>>(t2, h_nodes);

    // ---- graph readout ----
    pool<<<128, 256>>>(gp, h_nodes, out);

    (void)in_sizes; (void)n_in; (void)out_size;
}

// round 3
// speedup vs baseline: 1.2300x; 1.0307x over previous
#include <cuda_runtime.h>
#include <cstdint>

#define N_NODES 16384
#define HDIM    64
#define MAXN    160          // max nnz/row: Binomial(16384,0.004)+1, mean 66, ~11 sigma headroom
#define NBLK    1024         // gemm blocks (16 rows each)
#define BN_EPS  1e-5f

// ---------------- device scratch (no allocations allowed) ----------------
__device__ int   g_idx[N_NODES * MAXN];     // CSR-ish column indices per row
__device__ int   g_nnz[N_NODES];            // row degree (= row sum of adj)
__device__ float g_pooled[N_NODES * HDIM];
__device__ float g_t[N_NODES * HDIM];
__device__ float g_t2[N_NODES * HDIM];
__device__ float g_part[NBLK * 128];        // per-block [sum(64) | sumsq(64)]
__device__ float g_ab[128];                 // BN affine: a[64], b[64]

// ---------------- K0: no-op (ncu launch-index alignment: puts scan_adj at launch #6) ----------------
__global__ void noop_kernel() {}

// ---------------- K1: stream adj once, build index lists + degrees ----------------
__global__ __launch_bounds__(256) void scan_adj(const float* __restrict__ adj) {
    int lane   = threadIdx.x & 31;
    int wlocal = threadIdx.x >> 5;
    int row    = (blockIdx.x << 3) + wlocal;        // 2048 blocks * 8 warps

    __shared__ int snnz[8];
    if (lane == 0) snnz[wlocal] = 0;
    __syncwarp();

    const uint4* base = reinterpret_cast<const uint4*>(adj + (size_t)row * N_NODES);
    int* rowidx = g_idx + (size_t)row * MAXN;

    #pragma unroll 4
    for (int t = 0; t < 64; t++) {
        int f4 = t * 64 + lane * 2;                 // warp covers 1KB contiguous
        uint4 a = __ldcs(base + f4);                // streaming: evict-first
        uint4 b = __ldcs(base + f4 + 1);
        unsigned m = (a.x | a.y | a.z | a.w) | (b.x | b.y | b.z | b.w);
        if (m) {
            unsigned w[8] = {a.x, a.y, a.z, a.w, b.x, b.y, b.z, b.w};
            int col0 = f4 * 4;
            int loc[8];
            int cnt = 0;
            #pragma unroll
            for (int k = 0; k < 8; k++)
                if (w[k]) loc[cnt++] = col0 + k;
            int pos = atomicAdd(&snnz[wlocal], cnt);
            if (pos + cnt <= MAXN) {
                for (int i = 0; i < cnt; i++) rowidx[pos + i] = loc[i];
            }
        }
    }
    __syncwarp();
    if (lane == 0) g_nnz[row] = snnz[wlocal];
}

// ---------------- K2: sparse mean aggregation (4 rows per 256-thread block) ----------------
// out[r,:] = mean_{j in nbr(r)} f(src[j,:]);  f = identity (APPLY=0) or
// relu(a*x+b) using g_ab (APPLY=1, fuses previous layer's outer BN+ReLU).
template <int APPLY>
__global__ __launch_bounds__(256) void agg(const float* __restrict__ src,
                                           float* __restrict__ out) {
    int rl = threadIdx.x >> 6;              // 0..3 row within block
    int c  = threadIdx.x & 63;              // column
    int r  = (blockIdx.x << 2) + rl;

    __shared__ int ids[4][MAXN];
    int nnz = g_nnz[r];
    for (int i = c; i < nnz; i += 64) ids[rl][i] = g_idx[(size_t)r * MAXN + i];
    __syncthreads();

    float bn_a = 0.f, bn_b = 0.f;
    if (APPLY) { bn_a = g_ab[c]; bn_b = g_ab[64 + c]; }

    float a0 = 0.f, a1 = 0.f, a2 = 0.f, a3 = 0.f;
    int k = 0;
    for (; k + 4 <= nnz; k += 4) {
        float v0 = src[(size_t)ids[rl][k]     * HDIM + c];
        float v1 = src[(size_t)ids[rl][k + 1] * HDIM + c];
        float v2 = src[(size_t)ids[rl][k + 2] * HDIM + c];
        float v3 = src[(size_t)ids[rl][k + 3] * HDIM + c];
        if (APPLY) {
            v0 = fmaxf(fmaf(bn_a, v0, bn_b), 0.f);
            v1 = fmaxf(fmaf(bn_a, v1, bn_b), 0.f);
            v2 = fmaxf(fmaf(bn_a, v2, bn_b), 0.f);
            v3 = fmaxf(fmaf(bn_a, v3, bn_b), 0.f);
        }
        a0 += v0; a1 += v1; a2 += v2; a3 += v3;
    }
    for (; k < nnz; k++) {
        float v = src[(size_t)ids[rl][k] * HDIM + c];
        if (APPLY) v = fmaxf(fmaf(bn_a, v, bn_b), 0.f);
        a0 += v;
    }
    out[(size_t)r * HDIM + c] = ((a0 + a1) + (a2 + a3)) / (float)nnz;
}

// ---------------- K3: fused GEMM [16384,64]@[64,64] + bias + BN-stat partials
// MODE==1 applies relu(a*x+b) (previous inner BN) to the input tile.
template <int MODE>
__global__ __launch_bounds__(256) void gemm64(const float* __restrict__ in,
                                              const float* __restrict__ W,
                                              const float* __restrict__ bias,
                                              float* __restrict__ out,
                                              float* __restrict__ part) {
    __shared__ float Ws[64 * 64];
    __shared__ float Is[16][68];            // padded vs bank conflicts

    int tid = threadIdx.x;
    for (int i = tid; i < 4096; i += 256) Ws[i] = W[i];

    int row0 = blockIdx.x * 16;
    for (int i = tid; i < 1024; i += 256) {
        int rr = i >> 6, cc = i & 63;
        float v = in[(size_t)(row0 + rr) * HDIM + cc];
        if (MODE == 1)
            v = fmaxf(fmaf(g_ab[cc], v, g_ab[64 + cc]), 0.f);
        Is[rr][cc] = v;
    }
    __syncthreads();

    int ty = tid >> 4;          // output row within tile
    int tx = tid & 15;          // 4-col group
    float acc[4];
    #pragma unroll
    for (int j = 0; j < 4; j++) acc[j] = bias[tx * 4 + j];

    #pragma unroll
    for (int k = 0; k < 64; k++) {
        float iv = Is[ty][k];
        #pragma unroll
        for (int j = 0; j < 4; j++)
            acc[j] = fmaf(iv, Ws[k * 64 + tx * 4 + j], acc[j]);
    }

    size_t obase = (size_t)(row0 + ty) * HDIM + tx * 4;
    #pragma unroll
    for (int j = 0; j < 4; j++) out[obase + j] = acc[j];

    // per-block column stats (sum, sumsq) -> g_part (deterministic, no atomics)
    __syncthreads();
    #pragma unroll
    for (int j = 0; j < 4; j++) Is[ty][tx * 4 + j] = acc[j];
    __syncthreads();
    if (tid < 64) {
        float s = 0.f;
        #pragma unroll
        for (int r = 0; r < 16; r++) s += Is[r][tid];
        part[(size_t)blockIdx.x * 128 + tid] = s;
    }
    __syncthreads();
    #pragma unroll
    for (int j = 0; j < 4; j++) Is[ty][tx * 4 + j] = acc[j] * acc[j];
    __syncthreads();
    if (tid < 64) {
        float s = 0.f;
        #pragma unroll
        for (int r = 0; r < 16; r++) s += Is[r][tid];
        part[(size_t)blockIdx.x * 128 + 64 + tid] = s;
    }
}

// ---------------- K4: reduce partials -> BN affine coefficients ----------------
// grid=64 (one block per column), 256 threads stride the 1024 gemm blocks.
__global__ __launch_bounds__(256) void bn_finalize(const float* __restrict__ g,
                                                   const float* __restrict__ be) {
    int c = blockIdx.x;                      // column 0..63
    int t = threadIdx.x;

    float s = 0.f, q = 0.f;
    #pragma unroll 4
    for (int b = t; b < NBLK; b += 256) {
        s += g_part[(size_t)b * 128 + c];
        q += g_part[(size_t)b * 128 + 64 + c];
    }
    __shared__ float ss[256];
    __shared__ float qq[256];
    ss[t] = s; qq[t] = q;
    __syncthreads();
    #pragma unroll
    for (int o = 128; o > 0; o >>= 1) {
        if (t < o) { ss[t] += ss[t + o]; qq[t] += qq[t + o]; }
        __syncthreads();
    }
    if (t == 0) {
        const float invn = 1.0f / (float)N_NODES;
        float mean = ss[0] * invn;
        float var  = qq[0] * invn - mean * mean;
        float a = g[c] * rsqrtf(var + BN_EPS);
        g_ab[c]      = a;
        g_ab[64 + c] = be[c] - mean * a;
    }
}

// ---------------- K5: elementwise h = relu(a*t2 + b) (final layer only) ----------------
__global__ __launch_bounds__(256) void apply_bn_relu(const float* __restrict__ t2,
                                                     float* __restrict__ h) {
    int i = blockIdx.x * 256 + threadIdx.x;
    int c = i & 63;
    h[i] = fmaxf(fmaf(g_ab[c], t2[i], g_ab[64 + c]), 0.f);
}

// ---------------- K6: pooled_h = graph_pool @ h  (general dense, zero-skip) ----------------
__global__ __launch_bounds__(256) void pool(const float* __restrict__ gp,
                                            const float* __restrict__ h,
                                            float* __restrict__ out) {
    int g = blockIdx.x;                 // 128 graphs
    int c    = threadIdx.x & 63;
    int lane = threadIdx.x >> 6;        // 4 node-lanes (warp-uniform)
    const float* gprow = gp + (size_t)g * N_NODES;

    float acc = 0.f;
    for (int n0 = lane; n0 < N_NODES; n0 += 32) {
        #pragma unroll
        for (int u = 0; u < 8; u++) {
            int n = n0 + u * 4;
            float w = __ldcs(gprow + n);
            if (w != 0.f) acc = fmaf(w, h[(size_t)n * HDIM + c], acc);
        }
    }
    __shared__ float red[4][64];
    red[lane][c] = acc;
    __syncthreads();
    if (threadIdx.x < 64)
        out[(size_t)g * HDIM + threadIdx.x] =
            (red[0][threadIdx.x] + red[1][threadIdx.x]) +
            (red[2][threadIdx.x] + red[3][threadIdx.x]);
}

// ---------------- launch ----------------
extern "C" void kernel_launch(void* const* d_in, const int* in_sizes, int n_in,
                              void* d_out, int out_size) {
    const float* x   = (const float*)d_in[0];
    const float* adj = (const float*)d_in[1];
    const float* gp  = (const float*)d_in[2];

    const float* P[16];
    for (int i = 0; i < 16; i++) P[i] = (const float*)d_in[3 + i];

    float* out      = (float*)d_out;
    float* h_nodes  = out + 128 * HDIM;   // [16384,64] after the [128,64] readout

    float *pooled, *t, *t2, *part;
    cudaGetSymbolAddress((void**)&pooled, g_pooled);
    cudaGetSymbolAddress((void**)&t,      g_t);
    cudaGetSymbolAddress((void**)&t2,     g_t2);
    cudaGetSymbolAddress((void**)&part,   g_part);

    // 5 no-op launches: align scan_adj to launch #6 for the fixed ncu -s 5 -c 1
    // capture window (diagnostic; remove once scan_adj is characterized).
    for (int i = 0; i < 5; i++) noop_kernel<<<1, 32>>>();

    // 1) one pass over adj -> CSR indices + degrees
    scan_adj<<<2048, 256>>>(adj);

    // ---- layer 0 ----
    agg<0><<<N_NODES / 4, 256>>>(x, pooled);
    gemm64<0><<<NBLK, 256>>>(pooled, P[0], P[1], t, part);
    bn_finalize<<<64, 256>>>(P[2], P[3]);               // g1_0, be1_0
    gemm64<1><<<NBLK, 256>>>(t, P[4], P[5], t2, part);
    bn_finalize<<<64, 256>>>(P[6], P[7]);               // g_0, be_0

    // ---- layer 1 (outer BN+ReLU of layer 0 fused into the gather) ----
    agg<1><<<N_NODES / 4, 256>>>(t2, pooled);
    gemm64<0><<<NBLK, 256>>>(pooled, P[8], P[9], t, part);
    bn_finalize<<<64, 256>>>(P[10], P[11]);             // g1_1, be1_1
    gemm64<1><<<NBLK, 256>>>(t, P[12], P[13], t2, part);
    bn_finalize<<<64, 256>>>(P[14], P[15]);             // g_1, be_1
    apply_bn_relu<<<(N_NODES * HDIM) / 256, 256>>>(t2, h_nodes);

    // ---- graph readout ----
    pool<<<128, 256>>>(gp, h_nodes, out);

    (void)in_sizes; (void)n_in; (void)out_size;
}

// round 4
// speedup vs baseline: 1.2415x; 1.0093x over previous
#include <cuda_runtime.h>
#include <cstdint>

#define N_NODES 16384
#define HDIM    64
#define MAXN    160          // max nnz/row: Binomial(16384,0.004)+1, mean 66, ~11 sigma headroom
#define NBLK    1024         // gemm blocks (16 rows each)
#define BN_EPS  1e-5f

#define CHUNK_BYTES  16384   // 16KB per TMA chunk
#define CHUNK_FLOATS 4096
#define NCHUNK       4       // 64KB row = 4 chunks
#define NSTAGE       2       // double buffer

// ---------------- device scratch (no allocations allowed) ----------------
__device__ int   g_idx[N_NODES * MAXN];     // CSR-ish column indices per row
__device__ int   g_nnz[N_NODES];            // row degree (= row sum of adj)
__device__ float g_pooled[N_NODES * HDIM];
__device__ float g_t[N_NODES * HDIM];
__device__ float g_t2[N_NODES * HDIM];
__device__ float g_part[NBLK * 128];        // per-block [sum(64) | sumsq(64)]
__device__ float g_ab[128];                 // BN affine: a[64], b[64]

// ---------------- PTX helpers ----------------
__device__ __forceinline__ uint32_t smem_u32(const void* p) {
    uint32_t a;
    asm("{ .reg .u64 t; cvta.to.shared.u64 t, %1; cvt.u32.u64 %0, t; }"
        : "=r"(a) : "l"(p));
    return a;
}
__device__ __forceinline__ void mbar_init(uint32_t mbar, uint32_t count) {
    asm volatile("mbarrier.init.shared.b64 [%0], %1;" :: "r"(mbar), "r"(count) : "memory");
}
__device__ __forceinline__ void mbar_expect_tx(uint32_t mbar, uint32_t bytes) {
    asm volatile("mbarrier.arrive.expect_tx.shared.b64 _, [%0], %1;"
                 :: "r"(mbar), "r"(bytes) : "memory");
}
__device__ __forceinline__ void mbar_wait(uint32_t mbar, uint32_t parity) {
    uint32_t done;
    asm volatile(
        "{\n\t"
        ".reg .pred p;\n\t"
        "mbarrier.try_wait.parity.acquire.cta.shared::cta.b64 p, [%1], %2;\n\t"
        "selp.b32 %0, 1, 0, p;\n\t"
        "}"
        : "=r"(done) : "r"(mbar), "r"(parity) : "memory");
    if (!done) {
        asm volatile(
            "{\n\t"
            ".reg .pred P1;\n\t"
            "WL_%=:\n\t"
            "mbarrier.try_wait.parity.acquire.cta.shared::cta.b64 P1, [%0], %1, 0x989680;\n\t"
            "@P1 bra.uni WD_%=;\n\t"
            "bra.uni WL_%=;\n\t"
            "WD_%=:\n\t"
            "}"
            :: "r"(mbar), "r"(parity) : "memory");
    }
}
__device__ __forceinline__ void tma_bulk_g2s(uint32_t dst_smem, const void* src,
                                             uint32_t bytes, uint32_t mbar) {
    asm volatile(
        "cp.async.bulk.shared::cta.global.mbarrier::complete_tx::bytes [%0], [%1], %2, [%3];"
        :: "r"(dst_smem), "l"(src), "r"(bytes), "r"(mbar) : "memory");
}

// ---------------- K1: TMA-streamed adjacency scan ----------------
// One CTA per row (64KB). TMA bulk-copies 16KB chunks into a double-buffered
// SMEM ring (bypasses the per-SM LDG issue floor); 256 threads scan each chunk
// via LDS.128 and compact nonzero column indices.
__global__ __launch_bounds__(256) void scan_adj(const float* __restrict__ adj) {
    __shared__ __align__(128) uint4 buf[NSTAGE][CHUNK_FLOATS / 4];
    __shared__ __align__(16) uint64_t mbar_s[NSTAGE];
    __shared__ int snnz;

    int row = blockIdx.x;
    int tid = threadIdx.x;
    uint32_t mbar[NSTAGE];
    mbar[0] = smem_u32(&mbar_s[0]);
    mbar[1] = smem_u32(&mbar_s[1]);

    if (tid == 0) {
        snnz = 0;
        mbar_init(mbar[0], 1);
        mbar_init(mbar[1], 1);
    }
    __syncthreads();

    const char* src = reinterpret_cast<const char*>(adj) + (size_t)row * (N_NODES * 4);
    int* rowidx = g_idx + (size_t)row * MAXN;

    // prime the pipeline
    if (tid == 0) {
        mbar_expect_tx(mbar[0], CHUNK_BYTES);
        tma_bulk_g2s(smem_u32(&buf[0][0]), src, CHUNK_BYTES, mbar[0]);
        mbar_expect_tx(mbar[1], CHUNK_BYTES);
        tma_bulk_g2s(smem_u32(&buf[1][0]), src + CHUNK_BYTES, CHUNK_BYTES, mbar[1]);
    }

    for (int c = 0; c < NCHUNK; c++) {
        int s = c & 1;
        mbar_wait(mbar[s], (c >> 1) & 1);

        // scan 16KB: 256 threads x 4 x LDS.128
        #pragma unroll
        for (int j = 0; j < 4; j++) {
            uint4 v = buf[s][tid + j * 256];
            if (v.x | v.y | v.z | v.w) {
                int col0 = c * CHUNK_FLOATS + (tid + j * 256) * 4;
                unsigned w[4] = {v.x, v.y, v.z, v.w};
                int loc[4];
                int cnt = 0;
                #pragma unroll
                for (int k = 0; k < 4; k++)
                    if (w[k]) loc[cnt++] = col0 + k;
                int pos = atomicAdd(&snnz, cnt);
                if (pos + cnt <= MAXN)
                    for (int i = 0; i < cnt; i++) rowidx[pos + i] = loc[i];
            }
        }
        __syncthreads();                 // all reads of buf[s] done

        int nxt = c + NSTAGE;
        if (nxt < NCHUNK && tid == 0) {
            mbar_expect_tx(mbar[s], CHUNK_BYTES);
            tma_bulk_g2s(smem_u32(&buf[s][0]), src + (size_t)nxt * CHUNK_BYTES,
                         CHUNK_BYTES, mbar[s]);
        }
    }
    if (tid == 0) g_nnz[row] = snnz;
}

// ---------------- K2: sparse mean aggregation (4 rows per 256-thread block) ----------------
// out[r,:] = mean_{j in nbr(r)} f(src[j,:]);  f = identity (APPLY=0) or
// relu(a*x+b) using g_ab (APPLY=1, fuses previous layer's outer BN+ReLU).
template <int APPLY>
__global__ __launch_bounds__(256) void agg(const float* __restrict__ src,
                                           float* __restrict__ out) {
    int rl = threadIdx.x >> 6;              // 0..3 row within block
    int c  = threadIdx.x & 63;              // column
    int r  = (blockIdx.x << 2) + rl;

    __shared__ int ids[4][MAXN];
    int nnz = g_nnz[r];
    for (int i = c; i < nnz; i += 64) ids[rl][i] = g_idx[(size_t)r * MAXN + i];
    __syncthreads();

    float bn_a = 0.f, bn_b = 0.f;
    if (APPLY) { bn_a = g_ab[c]; bn_b = g_ab[64 + c]; }

    float a0 = 0.f, a1 = 0.f, a2 = 0.f, a3 = 0.f;
    int k = 0;
    for (; k + 4 <= nnz; k += 4) {
        float v0 = src[(size_t)ids[rl][k]     * HDIM + c];
        float v1 = src[(size_t)ids[rl][k + 1] * HDIM + c];
        float v2 = src[(size_t)ids[rl][k + 2] * HDIM + c];
        float v3 = src[(size_t)ids[rl][k + 3] * HDIM + c];
        if (APPLY) {
            v0 = fmaxf(fmaf(bn_a, v0, bn_b), 0.f);
            v1 = fmaxf(fmaf(bn_a, v1, bn_b), 0.f);
            v2 = fmaxf(fmaf(bn_a, v2, bn_b), 0.f);
            v3 = fmaxf(fmaf(bn_a, v3, bn_b), 0.f);
        }
        a0 += v0; a1 += v1; a2 += v2; a3 += v3;
    }
    for (; k < nnz; k++) {
        float v = src[(size_t)ids[rl][k] * HDIM + c];
        if (APPLY) v = fmaxf(fmaf(bn_a, v, bn_b), 0.f);
        a0 += v;
    }
    out[(size_t)r * HDIM + c] = ((a0 + a1) + (a2 + a3)) / (float)nnz;
}

// ---------------- K3: fused GEMM [16384,64]@[64,64] + bias + BN-stat partials
// MODE==1 applies relu(a*x+b) (previous inner BN) to the input tile.
template <int MODE>
__global__ __launch_bounds__(256) void gemm64(const float* __restrict__ in,
                                              const float* __restrict__ W,
                                              const float* __restrict__ bias,
                                              float* __restrict__ out,
                                              float* __restrict__ part) {
    __shared__ float Ws[64 * 64];
    __shared__ float Is[16][68];            // padded vs bank conflicts

    int tid = threadIdx.x;
    for (int i = tid; i < 4096; i += 256) Ws[i] = W[i];

    int row0 = blockIdx.x * 16;
    for (int i = tid; i < 1024; i += 256) {
        int rr = i >> 6, cc = i & 63;
        float v = in[(size_t)(row0 + rr) * HDIM + cc];
        if (MODE == 1)
            v = fmaxf(fmaf(g_ab[cc], v, g_ab[64 + cc]), 0.f);
        Is[rr][cc] = v;
    }
    __syncthreads();

    int ty = tid >> 4;          // output row within tile
    int tx = tid & 15;          // 4-col group
    float acc[4];
    #pragma unroll
    for (int j = 0; j < 4; j++) acc[j] = bias[tx * 4 + j];

    #pragma unroll
    for (int k = 0; k < 64; k++) {
        float iv = Is[ty][k];
        #pragma unroll
        for (int j = 0; j < 4; j++)
            acc[j] = fmaf(iv, Ws[k * 64 + tx * 4 + j], acc[j]);
    }

    size_t obase = (size_t)(row0 + ty) * HDIM + tx * 4;
    #pragma unroll
    for (int j = 0; j < 4; j++) out[obase + j] = acc[j];

    // per-block column stats (sum, sumsq) -> g_part (deterministic, no atomics)
    __syncthreads();
    #pragma unroll
    for (int j = 0; j < 4; j++) Is[ty][tx * 4 + j] = acc[j];
    __syncthreads();
    if (tid < 64) {
        float s = 0.f;
        #pragma unroll
        for (int r = 0; r < 16; r++) s += Is[r][tid];
        part[(size_t)blockIdx.x * 128 + tid] = s;
    }
    __syncthreads();
    #pragma unroll
    for (int j = 0; j < 4; j++) Is[ty][tx * 4 + j] = acc[j] * acc[j];
    __syncthreads();
    if (tid < 64) {
        float s = 0.f;
        #pragma unroll
        for (int r = 0; r < 16; r++) s += Is[r][tid];
        part[(size_t)blockIdx.x * 128 + 64 + tid] = s;
    }
}

// ---------------- K4: reduce partials -> BN affine coefficients ----------------
// grid=64 (one block per column), 256 threads stride the 1024 gemm blocks.
__global__ __launch_bounds__(256) void bn_finalize(const float* __restrict__ g,
                                                   const float* __restrict__ be) {
    int c = blockIdx.x;                      // column 0..63
    int t = threadIdx.x;

    float s = 0.f, q = 0.f;
    #pragma unroll 4
    for (int b = t; b < NBLK; b += 256) {
        s += g_part[(size_t)b * 128 + c];
        q += g_part[(size_t)b * 128 + 64 + c];
    }
    __shared__ float ss[256];
    __shared__ float qq[256];
    ss[t] = s; qq[t] = q;
    __syncthreads();
    #pragma unroll
    for (int o = 128; o > 0; o >>= 1) {
        if (t < o) { ss[t] += ss[t + o]; qq[t] += qq[t + o]; }
        __syncthreads();
    }
    if (t == 0) {
        const float invn = 1.0f / (float)N_NODES;
        float mean = ss[0] * invn;
        float var  = qq[0] * invn - mean * mean;
        float a = g[c] * rsqrtf(var + BN_EPS);
        g_ab[c]      = a;
        g_ab[64 + c] = be[c] - mean * a;
    }
}

// ---------------- K5: elementwise h = relu(a*t2 + b) (final layer only) ----------------
__global__ __launch_bounds__(256) void apply_bn_relu(const float* __restrict__ t2,
                                                     float* __restrict__ h) {
    int i = blockIdx.x * 256 + threadIdx.x;
    int c = i & 63;
    h[i] = fmaxf(fmaf(g_ab[c], t2[i], g_ab[64 + c]), 0.f);
}

// ---------------- K6: pooled_h = graph_pool @ h  (general dense, zero-skip) ----------------
__global__ __launch_bounds__(256) void pool(const float* __restrict__ gp,
                                            const float* __restrict__ h,
                                            float* __restrict__ out) {
    int g = blockIdx.x;                 // 128 graphs
    int c    = threadIdx.x & 63;
    int lane = threadIdx.x >> 6;        // 4 node-lanes (warp-uniform)
    const float* gprow = gp + (size_t)g * N_NODES;

    float acc = 0.f;
    for (int n0 = lane; n0 < N_NODES; n0 += 32) {
        #pragma unroll
        for (int u = 0; u < 8; u++) {
            int n = n0 + u * 4;
            float w = __ldcs(gprow + n);
            if (w != 0.f) acc = fmaf(w, h[(size_t)n * HDIM + c], acc);
        }
    }
    __shared__ float red[4][64];
    red[lane][c] = acc;
    __syncthreads();
    if (threadIdx.x < 64)
        out[(size_t)g * HDIM + threadIdx.x] =
            (red[0][threadIdx.x] + red[1][threadIdx.x]) +
            (red[2][threadIdx.x] + red[3][threadIdx.x]);
}

// ---------------- launch ----------------
extern "C" void kernel_launch(void* const* d_in, const int* in_sizes, int n_in,
                              void* d_out, int out_size) {
    const float* x   = (const float*)d_in[0];
    const float* adj = (const float*)d_in[1];
    const float* gp  = (const float*)d_in[2];

    const float* P[16];
    for (int i = 0; i < 16; i++) P[i] = (const float*)d_in[3 + i];

    float* out      = (float*)d_out;
    float* h_nodes  = out + 128 * HDIM;   // [16384,64] after the [128,64] readout

    float *pooled, *t, *t2, *part;
    cudaGetSymbolAddress((void**)&pooled, g_pooled);
    cudaGetSymbolAddress((void**)&t,      g_t);
    cudaGetSymbolAddress((void**)&t2,     g_t2);
    cudaGetSymbolAddress((void**)&part,   g_part);

    // 1) one TMA-streamed pass over adj -> CSR indices + degrees
    scan_adj<<<N_NODES, 256>>>(adj);

    // ---- layer 0 ----
    agg<0><<<N_NODES / 4, 256>>>(x, pooled);
    gemm64<0><<<NBLK, 256>>>(pooled, P[0], P[1], t, part);
    bn_finalize<<<64, 256>>>(P[2], P[3]);               // g1_0, be1_0
    gemm64<1><<<NBLK, 256>>>(t, P[4], P[5], t2, part);
    bn_finalize<<<64, 256>>>(P[6], P[7]);               // g_0, be_0

    // ---- layer 1 (outer BN+ReLU of layer 0 fused into the gather) ----
    agg<1><<<N_NODES / 4, 256>>>(t2, pooled);
    gemm64<0><<<NBLK, 256>>>(pooled, P[8], P[9], t, part);
    bn_finalize<<<64, 256>>>(P[10], P[11]);             // g1_1, be1_1
    gemm64<1><<<NBLK, 256>>>(t, P[12], P[13], t2, part);
    bn_finalize<<<64, 256>>>(P[14], P[15]);             // g_1, be_1
    apply_bn_relu<<<(N_NODES * HDIM) / 256, 256>>>(t2, h_nodes);

    // ---- graph readout ----
    pool<<<128, 256>>>(gp, h_nodes, out);

    (void)in_sizes; (void)n_in; (void)out_size;
}